// round 15
// baseline (speedup 1.0000x reference)
#include <cuda_runtime.h>

// GACRF fused: softmax(C=19) -> encode(G=8) -> 3x3 dynamic filter -> decode ->
// logit - result.  Single kernel, 64x16 tile + 1px halo in smem.
//
// R14: stencil bank-conflict fix via warp shuffle. Bank-level accounting shows
// the q0/q5 scalar LDS in the 3x3 stencil are 4-way bank-conflicted (16B lane
// stride -> banks {3,7,...}), making the stencil 288 wf/warp and pinning L1tex
// at ~70% (the true plateau cause). q0 == left lane's qm.w and q5 == right
// lane's qm.x, so both now come from __shfl (separate pipe, zero L1 traffic),
// with predicated loads only at the 4 row-boundary lanes. Per (dr,g): 12 wf ->
// ~5 wf. Base: R8 geometry + 2-pass phase 1 (best measured) + R10 E-row decode.
//
// Shapes (fixed): b=4, C=19, G=8, H=W=512, K=3.

#define BATCH 4
#define NC 19
#define NG 8
#define IMH 512
#define IMW 512
#define HW (IMH * IMW)

#define TW 64            // output tile width
#define TH 16            // output tile height
#define EH (TH + 2)      // 18 extended rows (global y0-1 .. y0+16)
#define EWP 72           // padded extended width, covers global [x0-4, x0+68)
#define NPAIR (EH * 9)   // 162 phase-1 threads, each owns 2 adjacent 4-px groups
#define NTHREADS 256

// ---- packed f32x2 helpers (per-lane IEEE identical to scalar) ----
__device__ __forceinline__ float2 ffma2(float2 a, float2 b, float2 c) {
    float2 d;
    asm("fma.rn.f32x2 %0, %1, %2, %3;"
        : "=l"(*reinterpret_cast<unsigned long long*>(&d))
        : "l"(*reinterpret_cast<unsigned long long*>(&a)),
          "l"(*reinterpret_cast<unsigned long long*>(&b)),
          "l"(*reinterpret_cast<unsigned long long*>(&c)));
    return d;
}
__device__ __forceinline__ float2 fadd2(float2 a, float2 b) {
    float2 d;
    asm("add.rn.f32x2 %0, %1, %2;"
        : "=l"(*reinterpret_cast<unsigned long long*>(&d))
        : "l"(*reinterpret_cast<unsigned long long*>(&a)),
          "l"(*reinterpret_cast<unsigned long long*>(&b)));
    return d;
}
__device__ __forceinline__ float2 fmul2(float2 a, float2 b) {
    float2 d;
    asm("mul.rn.f32x2 %0, %1, %2;"
        : "=l"(*reinterpret_cast<unsigned long long*>(&d))
        : "l"(*reinterpret_cast<unsigned long long*>(&a)),
          "l"(*reinterpret_cast<unsigned long long*>(&b)));
    return d;
}

__global__ __launch_bounds__(NTHREADS, 3) void gacrf_fused_kernel(
    const float* __restrict__ Fk,     // [b,9,H,W]
    const float* __restrict__ logit,  // [b,C,H,W]
    const float* __restrict__ matrix, // [G,C]
    float* __restrict__ out)          // [b,C,H,W]
{
    __shared__ float2 EshD[NC][NG];                   // (E,E) dup pairs (phase 1)
    __shared__ __align__(16) float Esh4[NC][NG];      // E rows (phase-2 decode)
    __shared__ __align__(16) float Qg[NG][EH][EWP];   // 41472 B

    const int tid = threadIdx.x;
    const int bx = blockIdx.x, by = blockIdx.y, bz = blockIdx.z;

    // ---- E = softmax over G of 100*matrix (both formats) ----
    if (tid < NC) {
        const int c = tid;
        float m[NG];
        float mx = -1e30f;
        #pragma unroll
        for (int g = 0; g < NG; g++) {
            m[g] = 100.0f * matrix[g * NC + c];
            mx = fmaxf(mx, m[g]);
        }
        float s = 0.0f;
        #pragma unroll
        for (int g = 0; g < NG; g++) { m[g] = __expf(m[g] - mx); s += m[g]; }
        const float r = 1.0f / s;
        #pragma unroll
        for (int g = 0; g < NG; g++) {
            const float v = m[g] * r;
            EshD[c][g] = make_float2(v, v);
            Esh4[c][g] = v;
        }
    }
    __syncthreads();

    const int x0 = bx * TW;
    const int y0 = by * TH;
    const float* __restrict__ logit_b = logit + (size_t)bz * NC * HW;

    // ---- Phase 1 (R8): softmax+encode, 2 sequential 4-px passes/thread ----
    if (tid < NPAIR) {
        const int r  = tid / 9;
        const int j  = tid - r * 9;
        const int gy = y0 + r - 1;
        const bool rowok = (unsigned)gy < IMH;
        const float2 z2 = make_float2(0.f, 0.f);
        const float4 z4 = make_float4(0.f, 0.f, 0.f, 0.f);

        #pragma unroll
        for (int pass = 0; pass < 2; pass++) {
            const int gxb = x0 - 4 + 8 * j + 4 * pass;
            // 4-aligned group vs 512 image: fully inside or fully outside
            const bool v = rowok && ((unsigned)gxb < IMW);

            float2 a01[NG], a23[NG];
            #pragma unroll
            for (int g = 0; g < NG; g++) { a01[g] = z2; a23[g] = z2; }
            float2 s01 = z2, s23 = z2;

            const float* __restrict__ p = logit_b + (size_t)gy * IMW + gxb;

            #pragma unroll
            for (int c = 0; c < NC; c++) {
                const float4 v4 = v ? __ldg((const float4*)(p + (size_t)c * HW)) : z4;
                const float2 e01 = make_float2(__expf(v4.x), __expf(v4.y));
                const float2 e23 = make_float2(__expf(v4.z), __expf(v4.w));
                s01 = fadd2(s01, e01);
                s23 = fadd2(s23, e23);
                #pragma unroll
                for (int g = 0; g < NG; g++) {
                    const float2 E2 = EshD[c][g];
                    a01[g] = ffma2(E2, e01, a01[g]);
                    a23[g] = ffma2(E2, e23, a23[g]);
                }
            }
            const float2 r01 = make_float2(__frcp_rn(s01.x), __frcp_rn(s01.y));
            const float2 r23 = make_float2(__frcp_rn(s23.x), __frcp_rn(s23.y));

            #pragma unroll
            for (int g = 0; g < NG; g++) {
                float4 o = z4;
                if (v) {
                    const float2 q01 = fmul2(a01[g], r01);
                    const float2 q23 = fmul2(a23[g], r23);
                    o = make_float4(q01.x, q01.y, q23.x, q23.y);
                }
                *(float4*)&Qg[g][r][8 * j + 4 * pass] = o;
            }
        }
    }
    __syncthreads();

    // ---- Phase 2: 3x3 filter (shuffle-assisted) + E-row decode ----
    {
        const int y    = tid >> 4;         // 0..15 (warp = 2 rows x 16 groups)
        const int xg   = (tid & 15) << 2;  // 0,4,..,60
        const int gy   = y0 + y;
        const int lane = tid & 31;
        const bool leftEdge  = ((lane & 15) == 0);    // xg == 0
        const bool rightEdge = ((lane & 15) == 15);   // xg == 60

        const float* __restrict__ fp =
            Fk + (size_t)bz * 9 * HW + (size_t)gy * IMW + (x0 + xg);

        const float2 z2 = make_float2(0.f, 0.f);
        float2 filtT[4][4];                // [pixel][g-pair]: .x even g, .y odd g
        #pragma unroll
        for (int px = 0; px < 4; px++)
            #pragma unroll
            for (int gp = 0; gp < 4; gp++) filtT[px][gp] = z2;

        #pragma unroll
        for (int dr = 0; dr < 3; dr++) {
            const float4 fa = __ldcs((const float4*)(fp + (size_t)(dr * 3 + 0) * HW));
            const float4 fb = __ldcs((const float4*)(fp + (size_t)(dr * 3 + 1) * HW));
            const float4 fc = __ldcs((const float4*)(fp + (size_t)(dr * 3 + 2) * HW));
            const float* __restrict__ qrowbase = &Qg[0][y + dr][0];
            #pragma unroll
            for (int g = 0; g < NG; g++) {
                const int gp = g >> 1;
                const float* __restrict__ qrow = &Qg[g][y + dr][0];
                // aligned vector: ext cols xg+4 .. xg+7 (conflict-free LDS.128)
                const float4 qm = *(const float4*)(qrow + xg + 4);
                // neighbors via shuffle (no L1 traffic, no bank conflicts)
                float q0 = __shfl_up_sync(0xffffffffu, qm.w, 1);   // ext col xg+3
                float q5 = __shfl_down_sync(0xffffffffu, qm.x, 1); // ext col xg+8
                if (leftEdge)  q0 = qrow[3];    // ext col 3  (xg==0)
                if (rightEdge) q5 = qrow[68];   // ext col 68 (xg==60)
                if (g & 1) {
                    filtT[0][gp].y = fmaf(fa.x, q0,   fmaf(fb.x, qm.x, fmaf(fc.x, qm.y, filtT[0][gp].y)));
                    filtT[1][gp].y = fmaf(fa.y, qm.x, fmaf(fb.y, qm.y, fmaf(fc.y, qm.z, filtT[1][gp].y)));
                    filtT[2][gp].y = fmaf(fa.z, qm.y, fmaf(fb.z, qm.z, fmaf(fc.z, qm.w, filtT[2][gp].y)));
                    filtT[3][gp].y = fmaf(fa.w, qm.z, fmaf(fb.w, qm.w, fmaf(fc.w, q5,   filtT[3][gp].y)));
                } else {
                    filtT[0][gp].x = fmaf(fa.x, q0,   fmaf(fb.x, qm.x, fmaf(fc.x, qm.y, filtT[0][gp].x)));
                    filtT[1][gp].x = fmaf(fa.y, qm.x, fmaf(fb.y, qm.y, fmaf(fc.y, qm.z, filtT[1][gp].x)));
                    filtT[2][gp].x = fmaf(fa.z, qm.y, fmaf(fb.z, qm.z, fmaf(fc.z, qm.w, filtT[2][gp].x)));
                    filtT[3][gp].x = fmaf(fa.w, qm.z, fmaf(fb.w, qm.w, fmaf(fc.w, q5,   filtT[3][gp].x)));
                }
            }
            (void)qrowbase;
        }

        const float* __restrict__ lp = logit_b + (size_t)gy * IMW + (x0 + xg);
        float* __restrict__       op = out + (size_t)bz * NC * HW
                                           + (size_t)gy * IMW + (x0 + xg);
        #pragma unroll
        for (int c = 0; c < NC; c++) {
            const float4 Ea = *(const float4*)&Esh4[c][0];
            const float4 Eb = *(const float4*)&Esh4[c][4];
            const float2 Ep0 = make_float2(Ea.x, Ea.y);
            const float2 Ep1 = make_float2(Ea.z, Ea.w);
            const float2 Ep2 = make_float2(Eb.x, Eb.y);
            const float2 Ep3 = make_float2(Eb.z, Eb.w);
            float2 a0 = z2, a1 = z2, a2 = z2, a3 = z2;
            a0 = ffma2(Ep0, filtT[0][0], a0);
            a0 = ffma2(Ep1, filtT[0][1], a0);
            a0 = ffma2(Ep2, filtT[0][2], a0);
            a0 = ffma2(Ep3, filtT[0][3], a0);
            a1 = ffma2(Ep0, filtT[1][0], a1);
            a1 = ffma2(Ep1, filtT[1][1], a1);
            a1 = ffma2(Ep2, filtT[1][2], a1);
            a1 = ffma2(Ep3, filtT[1][3], a1);
            a2 = ffma2(Ep0, filtT[2][0], a2);
            a2 = ffma2(Ep1, filtT[2][1], a2);
            a2 = ffma2(Ep2, filtT[2][2], a2);
            a2 = ffma2(Ep3, filtT[2][3], a2);
            a3 = ffma2(Ep0, filtT[3][0], a3);
            a3 = ffma2(Ep1, filtT[3][1], a3);
            a3 = ffma2(Ep2, filtT[3][2], a3);
            a3 = ffma2(Ep3, filtT[3][3], a3);
            const float4 l4 = __ldg((const float4*)(lp + (size_t)c * HW));
            float4 o;
            o.x = l4.x - (a0.x + a0.y);
            o.y = l4.y - (a1.x + a1.y);
            o.z = l4.z - (a2.x + a2.y);
            o.w = l4.w - (a3.x + a3.y);
            __stcs((float4*)(op + (size_t)c * HW), o);
        }
    }
}

extern "C" void kernel_launch(void* const* d_in, const int* in_sizes, int n_in,
                              void* d_out, int out_size) {
    // Bind inputs by element count (robust to ordering):
    //   F: 9437184, logit: 19922944, matrix: 152
    const float* F      = nullptr;
    const float* logit  = nullptr;
    const float* matrix = nullptr;
    for (int i = 0; i < n_in; i++) {
        if (in_sizes[i] == 9437184)       F      = (const float*)d_in[i];
        else if (in_sizes[i] == 19922944) logit  = (const float*)d_in[i];
        else if (in_sizes[i] == 152)      matrix = (const float*)d_in[i];
    }
    float* out = (float*)d_out;

    dim3 grid(IMW / TW, IMH / TH, BATCH);   // (8, 32, 4)
    gacrf_fused_kernel<<<grid, NTHREADS>>>(F, logit, matrix, out);
}

// round 16
// speedup vs baseline: 1.1951x; 1.1951x over previous
#include <cuda_runtime.h>
#include <cuda_pipeline.h>

// GACRF fused: softmax(C=19) -> encode(G=8) -> 3x3 dynamic filter -> decode ->
// logit - result.  Single kernel, 64x16 tile + 1px halo in smem.
//
// R15: cp.async-pipelined phase 1. The plateau diagnosis: MLP is register-bound
// (80-reg ceiling allows ~4 in-flight LDG.128/warp) and R8's two softmax passes
// serialize two full DRAM trips. Phase-1 logit loads now flow through a
// 10-deep per-thread cp.async ring in smem (LDGSTS = zero register cost): one
// continuous 38-chunk stream, pass-B prefetch hidden under pass-A compute.
// Accumulators stay at 32 regs. Each thread reads only its own staged 16B ->
// wait_prior only, no barrier. Phase 2 = R8 verbatim (measured best).
//
// Shapes (fixed): b=4, C=19, G=8, H=W=512, K=3.

#define BATCH 4
#define NC 19
#define NG 8
#define IMH 512
#define IMW 512
#define HW (IMH * IMW)

#define TW 64            // output tile width
#define TH 16            // output tile height
#define EH (TH + 2)      // 18 extended rows (global y0-1 .. y0+16)
#define EWP 72           // padded extended width, covers global [x0-4, x0+68)
#define NPAIR (EH * 9)   // 162 phase-1 threads, each owns 2 adjacent 4-px groups
#define NTHREADS 256
#define DEPTH 10         // cp.async pipeline depth (channels in flight)

#define QG_BYTES    (NG * EH * EWP * 4)          // 41472
#define STAGE_BYTES (DEPTH * NPAIR * 16)         // 25920
#define SMEM_DYN    (QG_BYTES + STAGE_BYTES)     // 67392

// ---- packed f32x2 helpers (per-lane IEEE identical to scalar) ----
__device__ __forceinline__ float2 ffma2(float2 a, float2 b, float2 c) {
    float2 d;
    asm("fma.rn.f32x2 %0, %1, %2, %3;"
        : "=l"(*reinterpret_cast<unsigned long long*>(&d))
        : "l"(*reinterpret_cast<unsigned long long*>(&a)),
          "l"(*reinterpret_cast<unsigned long long*>(&b)),
          "l"(*reinterpret_cast<unsigned long long*>(&c)));
    return d;
}
__device__ __forceinline__ float2 fadd2(float2 a, float2 b) {
    float2 d;
    asm("add.rn.f32x2 %0, %1, %2;"
        : "=l"(*reinterpret_cast<unsigned long long*>(&d))
        : "l"(*reinterpret_cast<unsigned long long*>(&a)),
          "l"(*reinterpret_cast<unsigned long long*>(&b)));
    return d;
}
__device__ __forceinline__ float2 fmul2(float2 a, float2 b) {
    float2 d;
    asm("mul.rn.f32x2 %0, %1, %2;"
        : "=l"(*reinterpret_cast<unsigned long long*>(&d))
        : "l"(*reinterpret_cast<unsigned long long*>(&a)),
          "l"(*reinterpret_cast<unsigned long long*>(&b)));
    return d;
}

__global__ __launch_bounds__(NTHREADS, 3) void gacrf_fused_kernel(
    const float* __restrict__ Fk,     // [b,9,H,W]
    const float* __restrict__ logit,  // [b,C,H,W]
    const float* __restrict__ matrix, // [G,C]
    float* __restrict__ out)          // [b,C,H,W]
{
    extern __shared__ __align__(16) char smem_dyn[];
    float (*Qg)[EH][EWP] = reinterpret_cast<float (*)[EH][EWP]>(smem_dyn);
    float4* stageBuf     = reinterpret_cast<float4*>(smem_dyn + QG_BYTES);
    __shared__ float2 EshD[NC][NG];                   // (E,E) dup pairs

    const int tid = threadIdx.x;
    const int bx = blockIdx.x, by = blockIdx.y, bz = blockIdx.z;

    // ---- E = softmax over G of 100*matrix ----
    if (tid < NC) {
        const int c = tid;
        float m[NG];
        float mx = -1e30f;
        #pragma unroll
        for (int g = 0; g < NG; g++) {
            m[g] = 100.0f * matrix[g * NC + c];
            mx = fmaxf(mx, m[g]);
        }
        float s = 0.0f;
        #pragma unroll
        for (int g = 0; g < NG; g++) { m[g] = __expf(m[g] - mx); s += m[g]; }
        const float r = 1.0f / s;
        #pragma unroll
        for (int g = 0; g < NG; g++) {
            const float v = m[g] * r;
            EshD[c][g] = make_float2(v, v);
        }
    }
    __syncthreads();

    const int x0 = bx * TW;
    const int y0 = by * TH;
    const float* __restrict__ logit_b = logit + (size_t)bz * NC * HW;

    // ---- Phase 1: softmax+encode via cp.async channel pipeline ----
    // Global chunk index i = 0..37: i<19 -> group A channel i; else group B.
    if (tid < NPAIR) {
        const int r  = tid / 9;
        const int j  = tid - r * 9;
        const int gy = y0 + r - 1;
        const bool rowok = (unsigned)gy < IMH;
        const int gxA = x0 - 4 + 8 * j;
        // 4-aligned groups vs 512 image: fully inside or fully outside
        const bool vA = rowok && ((unsigned)gxA < IMW);
        const bool vB = rowok && ((unsigned)(gxA + 4) < IMW);
        const float* __restrict__ pA = logit_b + (size_t)gy * IMW + gxA;

        const float2 z2 = make_float2(0.f, 0.f);
        const float4 z4 = make_float4(0.f, 0.f, 0.f, 0.f);

        // prologue: fill pipeline with chunks 0..DEPTH-1 (all pass-A channels)
        #pragma unroll
        for (int i = 0; i < DEPTH; i++) {
            if (vA)
                __pipeline_memcpy_async(&stageBuf[(i % DEPTH) * NPAIR + tid],
                                        pA + (size_t)i * HW, 16);
            __pipeline_commit();
        }

        float2 a01[NG], a23[NG];
        float2 s01, s23;

        // ---- pass A: channels 0..18 of group A ----
        #pragma unroll
        for (int g = 0; g < NG; g++) { a01[g] = z2; a23[g] = z2; }
        s01 = z2; s23 = z2;
        #pragma unroll
        for (int c = 0; c < NC; c++) {
            __pipeline_wait_prior(DEPTH - 1);
            const float4 v4 = vA ? stageBuf[(c % DEPTH) * NPAIR + tid] : z4;
            const float2 e01 = make_float2(__expf(v4.x), __expf(v4.y));
            const float2 e23 = make_float2(__expf(v4.z), __expf(v4.w));
            s01 = fadd2(s01, e01);
            s23 = fadd2(s23, e23);
            #pragma unroll
            for (int g = 0; g < NG; g++) {
                const float2 E2 = EshD[c][g];
                a01[g] = ffma2(E2, e01, a01[g]);
                a23[g] = ffma2(E2, e23, a23[g]);
            }
            // prefetch chunk c+DEPTH (crosses into pass B for c >= 9)
            const int ii = c + DEPTH;
            if (ii < NC) {
                if (vA)
                    __pipeline_memcpy_async(&stageBuf[(ii % DEPTH) * NPAIR + tid],
                                            pA + (size_t)ii * HW, 16);
            } else {
                const int jj = ii - NC;     // pass-B channel (jj <= 9 here)
                if (vB)
                    __pipeline_memcpy_async(&stageBuf[(ii % DEPTH) * NPAIR + tid],
                                            pA + 4 + (size_t)jj * HW, 16);
            }
            __pipeline_commit();
        }
        {
            const float2 r01 = make_float2(__frcp_rn(s01.x), __frcp_rn(s01.y));
            const float2 r23 = make_float2(__frcp_rn(s23.x), __frcp_rn(s23.y));
            #pragma unroll
            for (int g = 0; g < NG; g++) {
                float4 o = z4;
                if (vA) {
                    const float2 q01 = fmul2(a01[g], r01);
                    const float2 q23 = fmul2(a23[g], r23);
                    o = make_float4(q01.x, q01.y, q23.x, q23.y);
                }
                *(float4*)&Qg[g][r][8 * j] = o;
            }
        }

        // ---- pass B: channels 0..18 of group B (pipeline never drained) ----
        #pragma unroll
        for (int g = 0; g < NG; g++) { a01[g] = z2; a23[g] = z2; }
        s01 = z2; s23 = z2;
        #pragma unroll
        for (int c = 0; c < NC; c++) {
            __pipeline_wait_prior(DEPTH - 1);
            const float4 v4 = vB ? stageBuf[((c + NC) % DEPTH) * NPAIR + tid] : z4;
            const float2 e01 = make_float2(__expf(v4.x), __expf(v4.y));
            const float2 e23 = make_float2(__expf(v4.z), __expf(v4.w));
            s01 = fadd2(s01, e01);
            s23 = fadd2(s23, e23);
            #pragma unroll
            for (int g = 0; g < NG; g++) {
                const float2 E2 = EshD[c][g];
                a01[g] = ffma2(E2, e01, a01[g]);
                a23[g] = ffma2(E2, e23, a23[g]);
            }
            const int jj = c + DEPTH;       // B-channel to prefetch
            if (jj < NC && vB)
                __pipeline_memcpy_async(&stageBuf[((jj + NC) % DEPTH) * NPAIR + tid],
                                        pA + 4 + (size_t)jj * HW, 16);
            __pipeline_commit();
        }
        {
            const float2 r01 = make_float2(__frcp_rn(s01.x), __frcp_rn(s01.y));
            const float2 r23 = make_float2(__frcp_rn(s23.x), __frcp_rn(s23.y));
            #pragma unroll
            for (int g = 0; g < NG; g++) {
                float4 o = z4;
                if (vB) {
                    const float2 q01 = fmul2(a01[g], r01);
                    const float2 q23 = fmul2(a23[g], r23);
                    o = make_float4(q01.x, q01.y, q23.x, q23.y);
                }
                *(float4*)&Qg[g][r][8 * j + 4] = o;
            }
        }
    }
    __syncthreads();

    // ---- Phase 2 (R8 verbatim): 3x3 filter + decode + subtract ----
    {
        const int y  = tid >> 4;           // 0..15
        const int xg = (tid & 15) << 2;    // 0,4,..,60
        const int gy = y0 + y;

        const float* __restrict__ fp =
            Fk + (size_t)bz * 9 * HW + (size_t)gy * IMW + (x0 + xg);

        const float2 z2 = make_float2(0.f, 0.f);
        float2 filt01[NG], filt23[NG];
        #pragma unroll
        for (int g = 0; g < NG; g++) { filt01[g] = z2; filt23[g] = z2; }

        // dr-outer: stage 3 F taps at a time (register diet for 3 CTAs/SM)
        #pragma unroll
        for (int dr = 0; dr < 3; dr++) {
            const float4 fa = __ldcs((const float4*)(fp + (size_t)(dr * 3 + 0) * HW));
            const float4 fb = __ldcs((const float4*)(fp + (size_t)(dr * 3 + 1) * HW));
            const float4 fc = __ldcs((const float4*)(fp + (size_t)(dr * 3 + 2) * HW));
            #pragma unroll
            for (int g = 0; g < NG; g++) {
                const float* __restrict__ qrow = &Qg[g][y + dr][xg + 3];
                const float  q0 = qrow[0];
                const float4 qm = *(const float4*)(qrow + 1);
                const float  q5 = qrow[5];
                filt01[g].x = fmaf(fa.x, q0,   fmaf(fb.x, qm.x, fmaf(fc.x, qm.y, filt01[g].x)));
                filt01[g].y = fmaf(fa.y, qm.x, fmaf(fb.y, qm.y, fmaf(fc.y, qm.z, filt01[g].y)));
                filt23[g].x = fmaf(fa.z, qm.y, fmaf(fb.z, qm.z, fmaf(fc.z, qm.w, filt23[g].x)));
                filt23[g].y = fmaf(fa.w, qm.z, fmaf(fb.w, qm.w, fmaf(fc.w, q5,   filt23[g].y)));
            }
        }

        const float* __restrict__ lp = logit_b + (size_t)gy * IMW + (x0 + xg);
        float* __restrict__       op = out + (size_t)bz * NC * HW
                                           + (size_t)gy * IMW + (x0 + xg);
        #pragma unroll
        for (int c = 0; c < NC; c++) {
            float2 a01 = z2, a23 = z2;
            #pragma unroll
            for (int g = 0; g < NG; g++) {
                const float2 E2 = EshD[c][g];
                a01 = ffma2(E2, filt01[g], a01);
                a23 = ffma2(E2, filt23[g], a23);
            }
            const float4 l4 = __ldg((const float4*)(lp + (size_t)c * HW));
            float4 o;
            o.x = l4.x - a01.x; o.y = l4.y - a01.y;
            o.z = l4.z - a23.x; o.w = l4.w - a23.y;
            __stcs((float4*)(op + (size_t)c * HW), o);
        }
    }
}

extern "C" void kernel_launch(void* const* d_in, const int* in_sizes, int n_in,
                              void* d_out, int out_size) {
    // Bind inputs by element count (robust to ordering):
    //   F: 9437184, logit: 19922944, matrix: 152
    const float* F      = nullptr;
    const float* logit  = nullptr;
    const float* matrix = nullptr;
    for (int i = 0; i < n_in; i++) {
        if (in_sizes[i] == 9437184)       F      = (const float*)d_in[i];
        else if (in_sizes[i] == 19922944) logit  = (const float*)d_in[i];
        else if (in_sizes[i] == 152)      matrix = (const float*)d_in[i];
    }
    float* out = (float*)d_out;

    cudaFuncSetAttribute(gacrf_fused_kernel,
                         cudaFuncAttributeMaxDynamicSharedMemorySize, SMEM_DYN);

    dim3 grid(IMW / TW, IMH / TH, BATCH);   // (8, 32, 4)
    gacrf_fused_kernel<<<grid, NTHREADS, SMEM_DYN>>>(F, logit, matrix, out);
}